// round 9
// baseline (speedup 1.0000x reference)
#include <cuda_runtime.h>
#include <cuda_fp16.h>

// BilateralSliceApply on GB300 — R9: R8 (fp16 SMEM + HFMA2 taps) + per-pixel
// x-interp LUT in SMEM + 5 CTAs/SM for latency hiding.
// grid:  (4, 12, 8, 16, 16) f32
// guide: (4, 1024, 1024) f32
// image: (4, 3, 1024, 1024) f32
// out:   (4, 3, 1024, 1024) f32

#define GD 8
#define GH 16
#define GW 16
#define NC 12
#define W_IMG 1024
#define H_IMG 1024
#define GRID_PER_B (NC * GD * GH * GW)   // 24576
#define ROWS_PER_BLOCK 4

// fp16 SMEM layout in half2 (uint) units:
//   cell (z,x): 6 half2 used, padded to 8 (32 B)     -> XU = 8
//   z-slice: 16 cells * 32 B = 512 B + 16 B pad = 528 B (132 uints) -> ZU = 132
//   528 mod 128 = 16  =>  distinct 16-B bank group per z within an x-uniform phase.
#define XU 8
#define ZU 132
#define ROW_U (GD * ZU)   // 1056 uints per row buffer (4224 B)

__device__ __forceinline__ __half2 u2h(unsigned int u) {
    __half2 h;
    *reinterpret_cast<unsigned int*>(&h) = u;
    return h;
}

// one tap: 12 halves = uint4 (c0..c7) + uint2 (c8..c11), hfma2 into 6 fp16 accumulators
__device__ __forceinline__ void taph(const unsigned int* __restrict__ buf, int off,
                                     __half2 w2, __half2* acc) {
    const uint4 q  = *reinterpret_cast<const uint4*>(buf + off);
    const uint2 q2 = *reinterpret_cast<const uint2*>(buf + off + 4);
    acc[0] = __hfma2(u2h(q.x),  w2, acc[0]);
    acc[1] = __hfma2(u2h(q.y),  w2, acc[1]);
    acc[2] = __hfma2(u2h(q.z),  w2, acc[2]);
    acc[3] = __hfma2(u2h(q.w),  w2, acc[3]);
    acc[4] = __hfma2(u2h(q2.x), w2, acc[4]);
    acc[5] = __hfma2(u2h(q2.y), w2, acc[5]);
}

__global__ void __launch_bounds__(256, 5) bsa_kernel(
    const float* __restrict__ grid,
    const float* __restrict__ guide,
    const float* __restrict__ image,
    float* __restrict__ out)
{
    __shared__ __align__(16) unsigned int sg2[ROWS_PER_BLOCK][ROW_U];
    __shared__ __align__(16) uint4 xlut[W_IMG];   // {co0, co1, wx0, wx1} per pixel-x

    const int b   = blockIdx.y;
    const int tid = threadIdx.x;

    const float* gb = grid  + b * GRID_PER_B;
    const float* gu = guide + b * (H_IMG * W_IMG);
    const float* im = image + b * 3 * (H_IMG * W_IMG);
    float*       ob = out   + b * 3 * (H_IMG * W_IMG);

    const int row0 = blockIdx.x * ROWS_PER_BLOCK;

    // ---- build x-interp LUT: thread tid fills the 4 entries it will read ----
    #pragma unroll
    for (int j = 0; j < 4; ++j) {
        const int px = tid + (j << 8);
        const float gx  = ((float)px + 0.5f) * (16.0f / 1024.0f);
        const float fxm = floorf(gx - 0.5f);
        const float tx  = gx - 0.5f - fxm;
        const int   ifx = (int)fxm;
        const int   ix0 = min(max(ifx, 0), GW - 1);
        const int   ix1 = min(max(ifx + 1, 0), GW - 1);
        uint4 e;
        e.x = (unsigned)(ix0 * XU);
        e.y = (unsigned)(ix1 * XU);
        e.z = __float_as_uint(1.0f - tx);
        e.w = __float_as_uint(tx);
        xlut[px] = e;
    }

    // ---- stage all 4 rows: y-prefold in fp32, store fp16 pairs ----
    #pragma unroll
    for (int r = 0; r < ROWS_PER_BLOCK; ++r) {
        const int y = row0 + r;
        const float gyv = ((float)y + 0.5f) * (16.0f / 1024.0f);
        const float fym = floorf(gyv - 0.5f);
        const float ty  = gyv - 0.5f - fym;
        const int   ify = (int)fym;
        const int   iy0 = min(max(ify, 0), GH - 1);
        const int   iy1 = min(max(ify + 1, 0), GH - 1);
        const float wy0 = 1.0f - ty, wy1 = ty;

        // 768 channel-pairs per row: p = (cp*8 + z)*16 + x  (coalesced LDG over x)
        #pragma unroll
        for (int t = 0; t < 3; ++t) {
            const int p  = tid + t * 256;
            const int cp = p >> 7;
            const int z  = (p >> 4) & 7;
            const int x  = p & 15;
            const float* g0 = gb + (2 * cp)     * (GD * GH * GW) + z * (GH * GW) + x;
            const float* g1 = gb + (2 * cp + 1) * (GD * GH * GW) + z * (GH * GW) + x;
            const float f0 = wy0 * g0[iy0 * GW] + wy1 * g0[iy1 * GW];
            const float f1 = wy0 * g1[iy0 * GW] + wy1 * g1[iy1 * GW];
            __half2 h = __floats2half2_rn(f0, f1);
            sg2[r][z * ZU + x * XU + cp] = *reinterpret_cast<unsigned int*>(&h);
        }
    }
    __syncthreads();   // covers LUT + all staged rows

    // ---- process rows; lane tid owns pixels tid + 256*j ----
    #pragma unroll 1
    for (int r = 0; r < ROWS_PER_BLOCK; ++r) {
        const int y = row0 + r;
        const unsigned int* rowbuf = sg2[r];

        #pragma unroll
        for (int j = 0; j < 4; ++j) {
            const int px = tid + (j << 8);

            const float gvj = gu[y * W_IMG + px];
            const float R   = im[0 * 1048576 + y * W_IMG + px];
            const float G   = im[1 * 1048576 + y * W_IMG + px];
            const float Bc  = im[2 * 1048576 + y * W_IMG + px];

            // x interpolation from LUT
            const uint4 e  = xlut[px];
            const int   co0 = (int)e.x;
            const int   co1 = (int)e.y;
            const float wx0 = __uint_as_float(e.z);
            const float wx1 = __uint_as_float(e.w);

            // z interpolation (guide-driven)
            const float gz  = gvj * 8.0f;
            const float fzm = floorf(gz - 0.5f);
            const float tz  = gz - 0.5f - fzm;
            const int   ifz = (int)fzm;
            const int   iz0 = min(max(ifz, 0), GD - 1);
            const int   iz1 = min(max(ifz + 1, 0), GD - 1);
            const float wz0 = 1.0f - tz, wz1 = tz;

            const int zo0 = iz0 * ZU, zo1 = iz1 * ZU;

            __half2 acc[6];
            acc[0] = acc[1] = acc[2] = acc[3] = acc[4] = acc[5] =
                __half2half2(__ushort_as_half(0));

            taph(rowbuf, zo0 + co0, __float2half2_rn(wz0 * wx0), acc);
            taph(rowbuf, zo0 + co1, __float2half2_rn(wz0 * wx1), acc);
            taph(rowbuf, zo1 + co0, __float2half2_rn(wz1 * wx0), acc);
            taph(rowbuf, zo1 + co1, __float2half2_rn(wz1 * wx1), acc);

            const float2 p0 = __half22float2(acc[0]);
            const float2 p1 = __half22float2(acc[1]);
            const float2 p2 = __half22float2(acc[2]);
            const float2 p3 = __half22float2(acc[3]);
            const float2 p4 = __half22float2(acc[4]);
            const float2 p5 = __half22float2(acc[5]);

            ob[0 * 1048576 + y * W_IMG + px] =
                fmaf(p0.x, R, fmaf(p0.y, G, fmaf(p1.x, Bc, p1.y)));
            ob[1 * 1048576 + y * W_IMG + px] =
                fmaf(p2.x, R, fmaf(p2.y, G, fmaf(p3.x, Bc, p3.y)));
            ob[2 * 1048576 + y * W_IMG + px] =
                fmaf(p4.x, R, fmaf(p4.y, G, fmaf(p5.x, Bc, p5.y)));
        }
    }
}

extern "C" void kernel_launch(void* const* d_in, const int* in_sizes, int n_in,
                              void* d_out, int out_size)
{
    const float* grid  = nullptr;
    const float* guide = nullptr;
    const float* image = nullptr;
    for (int i = 0; i < n_in; ++i) {
        if (in_sizes[i] == 4 * GRID_PER_B)             grid  = (const float*)d_in[i];
        else if (in_sizes[i] == 4 * H_IMG * W_IMG)     guide = (const float*)d_in[i];
        else if (in_sizes[i] == 4 * 3 * H_IMG * W_IMG) image = (const float*)d_in[i];
    }
    float* out = (float*)d_out;

    dim3 gr(H_IMG / ROWS_PER_BLOCK, 4);   // 256 x 4 = 1024 blocks, 4 rows each
    bsa_kernel<<<gr, 256>>>(grid, guide, image, out);
}

// round 10
// speedup vs baseline: 1.7233x; 1.7233x over previous
#include <cuda_runtime.h>
#include <cuda_fp16.h>

// BilateralSliceApply on GB300 — R10: R8 fp16/HFMA2 core + float4 vectorized I/O.
// grid:  (4, 12, 8, 16, 16) f32
// guide: (4, 1024, 1024) f32
// image: (4, 3, 1024, 1024) f32
// out:   (4, 3, 1024, 1024) f32

#define GD 8
#define GH 16
#define GW 16
#define NC 12
#define W_IMG 1024
#define H_IMG 1024
#define GRID_PER_B (NC * GD * GH * GW)   // 24576
#define ROWS_PER_BLOCK 4

// fp16 SMEM layout in half2 (uint) units:
//   cell (z,x): 6 half2 used, padded to 8 (32 B)     -> XU = 8
//   z-slice: 16 cells * 32 B = 512 B + 16 B pad = 528 B (132 uints) -> ZU = 132
//   528 mod 128 = 16  =>  distinct 16-B bank group per z.
#define XU 8
#define ZU 132
#define ROW_U (GD * ZU)   // 1056 uints per row buffer (4224 B)

__device__ __forceinline__ __half2 u2h(unsigned int u) {
    __half2 h;
    *reinterpret_cast<unsigned int*>(&h) = u;
    return h;
}

// one tap: 12 halves = uint4 (c0..c7) + uint2 (c8..c11), hfma2 into 6 fp16 accumulators
__device__ __forceinline__ void taph(const unsigned int* __restrict__ buf, int off,
                                     __half2 w2, __half2* acc) {
    const uint4 q  = *reinterpret_cast<const uint4*>(buf + off);
    const uint2 q2 = *reinterpret_cast<const uint2*>(buf + off + 4);
    acc[0] = __hfma2(u2h(q.x),  w2, acc[0]);
    acc[1] = __hfma2(u2h(q.y),  w2, acc[1]);
    acc[2] = __hfma2(u2h(q.z),  w2, acc[2]);
    acc[3] = __hfma2(u2h(q.w),  w2, acc[3]);
    acc[4] = __hfma2(u2h(q2.x), w2, acc[4]);
    acc[5] = __hfma2(u2h(q2.y), w2, acc[5]);
}

__global__ void __launch_bounds__(256, 4) bsa_kernel(
    const float* __restrict__ grid,
    const float* __restrict__ guide,
    const float* __restrict__ image,
    float* __restrict__ out)
{
    __shared__ __align__(16) unsigned int sg2[ROWS_PER_BLOCK][ROW_U];

    const int b   = blockIdx.y;
    const int tid = threadIdx.x;

    const float* gb = grid  + b * GRID_PER_B;
    const float* gu = guide + b * (H_IMG * W_IMG);
    const float* im = image + b * 3 * (H_IMG * W_IMG);
    float*       ob = out   + b * 3 * (H_IMG * W_IMG);

    const int row0 = blockIdx.x * ROWS_PER_BLOCK;

    // ---- stage all 4 rows: y-prefold in fp32, store fp16 pairs; one barrier ----
    #pragma unroll
    for (int r = 0; r < ROWS_PER_BLOCK; ++r) {
        const int y = row0 + r;
        const float gyv = ((float)y + 0.5f) * (16.0f / 1024.0f);
        const float fym = floorf(gyv - 0.5f);
        const float ty  = gyv - 0.5f - fym;
        const int   ify = (int)fym;
        const int   iy0 = min(max(ify, 0), GH - 1);
        const int   iy1 = min(max(ify + 1, 0), GH - 1);
        const float wy0 = 1.0f - ty, wy1 = ty;

        // 768 channel-pairs per row: p = (cp*8 + z)*16 + x  (coalesced LDG over x)
        #pragma unroll
        for (int t = 0; t < 3; ++t) {
            const int p  = tid + t * 256;
            const int cp = p >> 7;
            const int z  = (p >> 4) & 7;
            const int x  = p & 15;
            const float* g0 = gb + (2 * cp)     * (GD * GH * GW) + z * (GH * GW) + x;
            const float* g1 = gb + (2 * cp + 1) * (GD * GH * GW) + z * (GH * GW) + x;
            const float f0 = wy0 * g0[iy0 * GW] + wy1 * g0[iy1 * GW];
            const float f1 = wy0 * g1[iy0 * GW] + wy1 * g1[iy1 * GW];
            __half2 h = __floats2half2_rn(f0, f1);
            sg2[r][z * ZU + x * XU + cp] = *reinterpret_cast<unsigned int*>(&h);
        }
    }
    __syncthreads();   // the only barrier

    // ---- process rows; lane tid owns float4 group x4 = tid (px 4*tid .. 4*tid+3) ----
    #pragma unroll 1
    for (int r = 0; r < ROWS_PER_BLOCK; ++r) {
        const int y = row0 + r;
        const unsigned int* rowbuf = sg2[r];

        const int x4  = tid;
        const int px0 = x4 << 2;

        const float4 g4 = reinterpret_cast<const float4*>(gu + y * W_IMG)[x4];
        const float4 r4 = reinterpret_cast<const float4*>(im + 0 * 1048576 + y * W_IMG)[x4];
        const float4 q4 = reinterpret_cast<const float4*>(im + 1 * 1048576 + y * W_IMG)[x4];
        const float4 b4 = reinterpret_cast<const float4*>(im + 2 * 1048576 + y * W_IMG)[x4];

        float4 outR, outG, outB;

        #pragma unroll
        for (int j = 0; j < 4; ++j) {
            const float gvj = (j == 0) ? g4.x : (j == 1) ? g4.y : (j == 2) ? g4.z : g4.w;
            const float R   = (j == 0) ? r4.x : (j == 1) ? r4.y : (j == 2) ? r4.z : r4.w;
            const float G   = (j == 0) ? q4.x : (j == 1) ? q4.y : (j == 2) ? q4.z : q4.w;
            const float Bc  = (j == 0) ? b4.x : (j == 1) ? b4.y : (j == 2) ? b4.z : b4.w;

            const int px = px0 + j;

            // x interpolation
            const float gx  = ((float)px + 0.5f) * (16.0f / 1024.0f);
            const float fxm = floorf(gx - 0.5f);
            const float tx  = gx - 0.5f - fxm;
            const int   ifx = (int)fxm;
            const int   ix0 = min(max(ifx, 0), GW - 1);
            const int   ix1 = min(max(ifx + 1, 0), GW - 1);
            const float wx0 = 1.0f - tx, wx1 = tx;

            // z interpolation (guide-driven)
            const float gz  = gvj * 8.0f;
            const float fzm = floorf(gz - 0.5f);
            const float tz  = gz - 0.5f - fzm;
            const int   ifz = (int)fzm;
            const int   iz0 = min(max(ifz, 0), GD - 1);
            const int   iz1 = min(max(ifz + 1, 0), GD - 1);
            const float wz0 = 1.0f - tz, wz1 = tz;

            const int zo0 = iz0 * ZU, zo1 = iz1 * ZU;
            const int co0 = ix0 * XU, co1 = ix1 * XU;

            __half2 acc[6];
            acc[0] = acc[1] = acc[2] = acc[3] = acc[4] = acc[5] =
                __half2half2(__ushort_as_half(0));

            taph(rowbuf, zo0 + co0, __float2half2_rn(wz0 * wx0), acc);
            taph(rowbuf, zo0 + co1, __float2half2_rn(wz0 * wx1), acc);
            taph(rowbuf, zo1 + co0, __float2half2_rn(wz1 * wx0), acc);
            taph(rowbuf, zo1 + co1, __float2half2_rn(wz1 * wx1), acc);

            const float2 p0 = __half22float2(acc[0]);
            const float2 p1 = __half22float2(acc[1]);
            const float2 p2 = __half22float2(acc[2]);
            const float2 p3 = __half22float2(acc[3]);
            const float2 p4 = __half22float2(acc[4]);
            const float2 p5 = __half22float2(acc[5]);

            const float vR = fmaf(p0.x, R, fmaf(p0.y, G, fmaf(p1.x, Bc, p1.y)));
            const float vG = fmaf(p2.x, R, fmaf(p2.y, G, fmaf(p3.x, Bc, p3.y)));
            const float vB = fmaf(p4.x, R, fmaf(p4.y, G, fmaf(p5.x, Bc, p5.y)));

            if (j == 0)      { outR.x = vR; outG.x = vG; outB.x = vB; }
            else if (j == 1) { outR.y = vR; outG.y = vG; outB.y = vB; }
            else if (j == 2) { outR.z = vR; outG.z = vG; outB.z = vB; }
            else             { outR.w = vR; outG.w = vG; outB.w = vB; }
        }

        reinterpret_cast<float4*>(ob + 0 * 1048576 + y * W_IMG)[x4] = outR;
        reinterpret_cast<float4*>(ob + 1 * 1048576 + y * W_IMG)[x4] = outG;
        reinterpret_cast<float4*>(ob + 2 * 1048576 + y * W_IMG)[x4] = outB;
    }
}

extern "C" void kernel_launch(void* const* d_in, const int* in_sizes, int n_in,
                              void* d_out, int out_size)
{
    const float* grid  = nullptr;
    const float* guide = nullptr;
    const float* image = nullptr;
    for (int i = 0; i < n_in; ++i) {
        if (in_sizes[i] == 4 * GRID_PER_B)             grid  = (const float*)d_in[i];
        else if (in_sizes[i] == 4 * H_IMG * W_IMG)     guide = (const float*)d_in[i];
        else if (in_sizes[i] == 4 * 3 * H_IMG * W_IMG) image = (const float*)d_in[i];
    }
    float* out = (float*)d_out;

    dim3 gr(H_IMG / ROWS_PER_BLOCK, 4);   // 256 x 4 = 1024 blocks, 4 rows each
    bsa_kernel<<<gr, 256>>>(grid, guide, image, out);
}

// round 11
// speedup vs baseline: 1.8250x; 1.0590x over previous
#include <cuda_runtime.h>
#include <cuda_fp16.h>

// BilateralSliceApply on GB300 — R11: R8 core (fp16 SMEM + HFMA2, strided px)
// with explicitly batched tap loads (all 6 LDS per pixel before any FMA) and
// hoisted guide loads to maximize memory-level parallelism.
// grid:  (4, 12, 8, 16, 16) f32
// guide: (4, 1024, 1024) f32
// image: (4, 3, 1024, 1024) f32
// out:   (4, 3, 1024, 1024) f32

#define GD 8
#define GH 16
#define GW 16
#define NC 12
#define W_IMG 1024
#define H_IMG 1024
#define GRID_PER_B (NC * GD * GH * GW)   // 24576
#define ROWS_PER_BLOCK 4

// fp16 SMEM layout in half2 (uint) units:
//   cell (z,x): 6 half2 used, padded to 8 (32 B)     -> XU = 8
//   z-slice: 16 cells * 32 B = 512 B + 16 B pad = 528 B (132 uints) -> ZU = 132
//   528 mod 128 = 16  =>  distinct 16-B bank group per z within an x-uniform phase.
#define XU 8
#define ZU 132
#define ROW_U (GD * ZU)   // 1056 uints per row buffer (4224 B)

__device__ __forceinline__ __half2 u2h(unsigned int u) {
    __half2 h;
    *reinterpret_cast<unsigned int*>(&h) = u;
    return h;
}

__global__ void __launch_bounds__(256, 4) bsa_kernel(
    const float* __restrict__ grid,
    const float* __restrict__ guide,
    const float* __restrict__ image,
    float* __restrict__ out)
{
    __shared__ __align__(16) unsigned int sg2[ROWS_PER_BLOCK][ROW_U];

    const int b   = blockIdx.y;
    const int tid = threadIdx.x;

    const float* gb = grid  + b * GRID_PER_B;
    const float* gu = guide + b * (H_IMG * W_IMG);
    const float* im = image + b * 3 * (H_IMG * W_IMG);
    float*       ob = out   + b * 3 * (H_IMG * W_IMG);

    const int row0 = blockIdx.x * ROWS_PER_BLOCK;

    // ---- stage all 4 rows: y-prefold in fp32, store fp16 pairs; one barrier ----
    #pragma unroll
    for (int r = 0; r < ROWS_PER_BLOCK; ++r) {
        const int y = row0 + r;
        const float gyv = ((float)y + 0.5f) * (16.0f / 1024.0f);
        const float fym = floorf(gyv - 0.5f);
        const float ty  = gyv - 0.5f - fym;
        const int   ify = (int)fym;
        const int   iy0 = min(max(ify, 0), GH - 1);
        const int   iy1 = min(max(ify + 1, 0), GH - 1);
        const float wy0 = 1.0f - ty, wy1 = ty;

        // 768 channel-pairs per row: p = (cp*8 + z)*16 + x  (coalesced LDG over x)
        #pragma unroll
        for (int t = 0; t < 3; ++t) {
            const int p  = tid + t * 256;
            const int cp = p >> 7;
            const int z  = (p >> 4) & 7;
            const int x  = p & 15;
            const float* g0 = gb + (2 * cp)     * (GD * GH * GW) + z * (GH * GW) + x;
            const float* g1 = gb + (2 * cp + 1) * (GD * GH * GW) + z * (GH * GW) + x;
            const float f0 = wy0 * g0[iy0 * GW] + wy1 * g0[iy1 * GW];
            const float f1 = wy0 * g1[iy0 * GW] + wy1 * g1[iy1 * GW];
            __half2 h = __floats2half2_rn(f0, f1);
            sg2[r][z * ZU + x * XU + cp] = *reinterpret_cast<unsigned int*>(&h);
        }
    }
    __syncthreads();   // the only barrier

    // ---- process rows; lane tid owns pixels tid + 256*j ----
    #pragma unroll 1
    for (int r = 0; r < ROWS_PER_BLOCK; ++r) {
        const int y = row0 + r;
        const unsigned int* rowbuf = sg2[r];
        const int rowoff = y * W_IMG;

        // hoist the 4 guide loads — head of the longest dependency chain
        float gv[4];
        #pragma unroll
        for (int j = 0; j < 4; ++j)
            gv[j] = gu[rowoff + tid + (j << 8)];

        #pragma unroll
        for (int j = 0; j < 4; ++j) {
            const int px = tid + (j << 8);

            const float R  = im[0 * 1048576 + rowoff + px];
            const float G  = im[1 * 1048576 + rowoff + px];
            const float Bc = im[2 * 1048576 + rowoff + px];

            // x interpolation
            const float gx  = ((float)px + 0.5f) * (16.0f / 1024.0f);
            const float fxm = floorf(gx - 0.5f);
            const float tx  = gx - 0.5f - fxm;
            const int   ifx = (int)fxm;
            const int   ix0 = min(max(ifx, 0), GW - 1);
            const int   ix1 = min(max(ifx + 1, 0), GW - 1);
            const float wx0 = 1.0f - tx, wx1 = tx;

            // z interpolation (guide-driven)
            const float gz  = gv[j] * 8.0f;
            const float fzm = floorf(gz - 0.5f);
            const float tz  = gz - 0.5f - fzm;
            const int   ifz = (int)fzm;
            const int   iz0 = min(max(ifz, 0), GD - 1);
            const int   iz1 = min(max(ifz + 1, 0), GD - 1);
            const float wz0 = 1.0f - tz, wz1 = tz;

            const int o0 = iz0 * ZU + ix0 * XU;   // (z0,x0)
            const int o1 = iz0 * ZU + ix1 * XU;   // (z0,x1)
            const int o2 = iz1 * ZU + ix0 * XU;   // (z1,x0)
            const int o3 = iz1 * ZU + ix1 * XU;   // (z1,x1)

            // ---- batch ALL tap loads first (6 LDS back-to-back) ----
            const uint4 qa = *reinterpret_cast<const uint4*>(rowbuf + o0);
            const uint4 qb = *reinterpret_cast<const uint4*>(rowbuf + o1);
            const uint4 qc = *reinterpret_cast<const uint4*>(rowbuf + o2);
            const uint4 qd = *reinterpret_cast<const uint4*>(rowbuf + o3);
            const uint2 ra = *reinterpret_cast<const uint2*>(rowbuf + o0 + 4);
            const uint2 rb = *reinterpret_cast<const uint2*>(rowbuf + o1 + 4);
            const uint2 rc = *reinterpret_cast<const uint2*>(rowbuf + o2 + 4);
            const uint2 rd = *reinterpret_cast<const uint2*>(rowbuf + o3 + 4);

            const __half2 wa = __float2half2_rn(wz0 * wx0);
            const __half2 wb = __float2half2_rn(wz0 * wx1);
            const __half2 wc = __float2half2_rn(wz1 * wx0);
            const __half2 wd = __float2half2_rn(wz1 * wx1);

            // ---- 24 HFMA2, no loads interleaved ----
            __half2 a0, a1, a2, a3, a4, a5;
            a0 = __hmul2(u2h(qa.x), wa);
            a1 = __hmul2(u2h(qa.y), wa);
            a2 = __hmul2(u2h(qa.z), wa);
            a3 = __hmul2(u2h(qa.w), wa);
            a4 = __hmul2(u2h(ra.x), wa);
            a5 = __hmul2(u2h(ra.y), wa);

            a0 = __hfma2(u2h(qb.x), wb, a0);
            a1 = __hfma2(u2h(qb.y), wb, a1);
            a2 = __hfma2(u2h(qb.z), wb, a2);
            a3 = __hfma2(u2h(qb.w), wb, a3);
            a4 = __hfma2(u2h(rb.x), wb, a4);
            a5 = __hfma2(u2h(rb.y), wb, a5);

            a0 = __hfma2(u2h(qc.x), wc, a0);
            a1 = __hfma2(u2h(qc.y), wc, a1);
            a2 = __hfma2(u2h(qc.z), wc, a2);
            a3 = __hfma2(u2h(qc.w), wc, a3);
            a4 = __hfma2(u2h(rc.x), wc, a4);
            a5 = __hfma2(u2h(rc.y), wc, a5);

            a0 = __hfma2(u2h(qd.x), wd, a0);
            a1 = __hfma2(u2h(qd.y), wd, a1);
            a2 = __hfma2(u2h(qd.z), wd, a2);
            a3 = __hfma2(u2h(qd.w), wd, a3);
            a4 = __hfma2(u2h(rd.x), wd, a4);
            a5 = __hfma2(u2h(rd.y), wd, a5);

            const float2 p0 = __half22float2(a0);
            const float2 p1 = __half22float2(a1);
            const float2 p2 = __half22float2(a2);
            const float2 p3 = __half22float2(a3);
            const float2 p4 = __half22float2(a4);
            const float2 p5 = __half22float2(a5);

            ob[0 * 1048576 + rowoff + px] =
                fmaf(p0.x, R, fmaf(p0.y, G, fmaf(p1.x, Bc, p1.y)));
            ob[1 * 1048576 + rowoff + px] =
                fmaf(p2.x, R, fmaf(p2.y, G, fmaf(p3.x, Bc, p3.y)));
            ob[2 * 1048576 + rowoff + px] =
                fmaf(p4.x, R, fmaf(p4.y, G, fmaf(p5.x, Bc, p5.y)));
        }
    }
}

extern "C" void kernel_launch(void* const* d_in, const int* in_sizes, int n_in,
                              void* d_out, int out_size)
{
    const float* grid  = nullptr;
    const float* guide = nullptr;
    const float* image = nullptr;
    for (int i = 0; i < n_in; ++i) {
        if (in_sizes[i] == 4 * GRID_PER_B)             grid  = (const float*)d_in[i];
        else if (in_sizes[i] == 4 * H_IMG * W_IMG)     guide = (const float*)d_in[i];
        else if (in_sizes[i] == 4 * 3 * H_IMG * W_IMG) image = (const float*)d_in[i];
    }
    float* out = (float*)d_out;

    dim3 gr(H_IMG / ROWS_PER_BLOCK, 4);   // 256 x 4 = 1024 blocks, 4 rows each
    bsa_kernel<<<gr, 256>>>(grid, guide, image, out);
}

// round 12
// speedup vs baseline: 1.8400x; 1.0082x over previous
#include <cuda_runtime.h>
#include <cuda_fp16.h>

// BilateralSliceApply on GB300 — R12: R11 core (fp16 SMEM + HFMA2, strided px,
// batched tap loads) with j-outer/row-inner loops so per-thread x-interpolation
// is computed once per pixel-column instead of once per (row, column).
// grid:  (4, 12, 8, 16, 16) f32
// guide: (4, 1024, 1024) f32
// image: (4, 3, 1024, 1024) f32
// out:   (4, 3, 1024, 1024) f32

#define GD 8
#define GH 16
#define GW 16
#define NC 12
#define W_IMG 1024
#define H_IMG 1024
#define GRID_PER_B (NC * GD * GH * GW)   // 24576
#define ROWS_PER_BLOCK 4

// fp16 SMEM layout in half2 (uint) units:
//   cell (z,x): 6 half2 used, padded to 8 (32 B)     -> XU = 8
//   z-slice: 16 cells * 32 B = 512 B + 16 B pad = 528 B (132 uints) -> ZU = 132
//   528 mod 128 = 16  =>  distinct 16-B bank group per z within an x-uniform phase.
#define XU 8
#define ZU 132
#define ROW_U (GD * ZU)   // 1056 uints per row buffer (4224 B)

__device__ __forceinline__ __half2 u2h(unsigned int u) {
    __half2 h;
    *reinterpret_cast<unsigned int*>(&h) = u;
    return h;
}

__global__ void __launch_bounds__(256, 4) bsa_kernel(
    const float* __restrict__ grid,
    const float* __restrict__ guide,
    const float* __restrict__ image,
    float* __restrict__ out)
{
    __shared__ __align__(16) unsigned int sg2[ROWS_PER_BLOCK][ROW_U];

    const int b   = blockIdx.y;
    const int tid = threadIdx.x;

    const float* gb = grid  + b * GRID_PER_B;
    const float* gu = guide + b * (H_IMG * W_IMG);
    const float* im = image + b * 3 * (H_IMG * W_IMG);
    float*       ob = out   + b * 3 * (H_IMG * W_IMG);

    const int row0 = blockIdx.x * ROWS_PER_BLOCK;

    // ---- stage all 4 rows: y-prefold in fp32, store fp16 pairs; one barrier ----
    #pragma unroll
    for (int r = 0; r < ROWS_PER_BLOCK; ++r) {
        const int y = row0 + r;
        const float gyv = ((float)y + 0.5f) * (16.0f / 1024.0f);
        const float fym = floorf(gyv - 0.5f);
        const float ty  = gyv - 0.5f - fym;
        const int   ify = (int)fym;
        const int   iy0 = min(max(ify, 0), GH - 1);
        const int   iy1 = min(max(ify + 1, 0), GH - 1);
        const float wy0 = 1.0f - ty, wy1 = ty;

        // 768 channel-pairs per row: p = (cp*8 + z)*16 + x  (coalesced LDG over x)
        #pragma unroll
        for (int t = 0; t < 3; ++t) {
            const int p  = tid + t * 256;
            const int cp = p >> 7;
            const int z  = (p >> 4) & 7;
            const int x  = p & 15;
            const float* g0 = gb + (2 * cp)     * (GD * GH * GW) + z * (GH * GW) + x;
            const float* g1 = gb + (2 * cp + 1) * (GD * GH * GW) + z * (GH * GW) + x;
            const float f0 = wy0 * g0[iy0 * GW] + wy1 * g0[iy1 * GW];
            const float f1 = wy0 * g1[iy0 * GW] + wy1 * g1[iy1 * GW];
            __half2 h = __floats2half2_rn(f0, f1);
            sg2[r][z * ZU + x * XU + cp] = *reinterpret_cast<unsigned int*>(&h);
        }
    }
    __syncthreads();   // the only barrier

    // ---- j outer (pixel column), rows inner: x-interp hoisted per column ----
    #pragma unroll
    for (int j = 0; j < 4; ++j) {
        const int px = tid + (j << 8);

        // x interpolation — loop-invariant over rows
        const float gx  = ((float)px + 0.5f) * (16.0f / 1024.0f);
        const float fxm = floorf(gx - 0.5f);
        const float tx  = gx - 0.5f - fxm;
        const int   ifx = (int)fxm;
        const int   ix0 = min(max(ifx, 0), GW - 1);
        const int   ix1 = min(max(ifx + 1, 0), GW - 1);
        const float wx0 = 1.0f - tx, wx1 = tx;
        const int   co0 = ix0 * XU, co1 = ix1 * XU;

        // batch the 4 guide loads (head of the longest dependency chain)
        float gv[ROWS_PER_BLOCK];
        #pragma unroll
        for (int r = 0; r < ROWS_PER_BLOCK; ++r)
            gv[r] = gu[(row0 + r) * W_IMG + px];

        #pragma unroll
        for (int r = 0; r < ROWS_PER_BLOCK; ++r) {
            const int y = row0 + r;
            const int rowoff = y * W_IMG;
            const unsigned int* rowbuf = sg2[r];

            const float R  = im[0 * 1048576 + rowoff + px];
            const float G  = im[1 * 1048576 + rowoff + px];
            const float Bc = im[2 * 1048576 + rowoff + px];

            // z interpolation (guide-driven)
            const float gz  = gv[r] * 8.0f;
            const float fzm = floorf(gz - 0.5f);
            const float tz  = gz - 0.5f - fzm;
            const int   ifz = (int)fzm;
            const int   iz0 = min(max(ifz, 0), GD - 1);
            const int   iz1 = min(max(ifz + 1, 0), GD - 1);
            const float wz0 = 1.0f - tz, wz1 = tz;

            const int o0 = iz0 * ZU + co0;   // (z0,x0)
            const int o1 = iz0 * ZU + co1;   // (z0,x1)
            const int o2 = iz1 * ZU + co0;   // (z1,x0)
            const int o3 = iz1 * ZU + co1;   // (z1,x1)

            // ---- batch ALL tap loads first (6 LDS back-to-back) ----
            const uint4 qa = *reinterpret_cast<const uint4*>(rowbuf + o0);
            const uint4 qb = *reinterpret_cast<const uint4*>(rowbuf + o1);
            const uint4 qc = *reinterpret_cast<const uint4*>(rowbuf + o2);
            const uint4 qd = *reinterpret_cast<const uint4*>(rowbuf + o3);
            const uint2 ra = *reinterpret_cast<const uint2*>(rowbuf + o0 + 4);
            const uint2 rb = *reinterpret_cast<const uint2*>(rowbuf + o1 + 4);
            const uint2 rc = *reinterpret_cast<const uint2*>(rowbuf + o2 + 4);
            const uint2 rd = *reinterpret_cast<const uint2*>(rowbuf + o3 + 4);

            const __half2 wa = __float2half2_rn(wz0 * wx0);
            const __half2 wb = __float2half2_rn(wz0 * wx1);
            const __half2 wc = __float2half2_rn(wz1 * wx0);
            const __half2 wd = __float2half2_rn(wz1 * wx1);

            // ---- 24 HFMA2, no loads interleaved ----
            __half2 a0, a1, a2, a3, a4, a5;
            a0 = __hmul2(u2h(qa.x), wa);
            a1 = __hmul2(u2h(qa.y), wa);
            a2 = __hmul2(u2h(qa.z), wa);
            a3 = __hmul2(u2h(qa.w), wa);
            a4 = __hmul2(u2h(ra.x), wa);
            a5 = __hmul2(u2h(ra.y), wa);

            a0 = __hfma2(u2h(qb.x), wb, a0);
            a1 = __hfma2(u2h(qb.y), wb, a1);
            a2 = __hfma2(u2h(qb.z), wb, a2);
            a3 = __hfma2(u2h(qb.w), wb, a3);
            a4 = __hfma2(u2h(rb.x), wb, a4);
            a5 = __hfma2(u2h(rb.y), wb, a5);

            a0 = __hfma2(u2h(qc.x), wc, a0);
            a1 = __hfma2(u2h(qc.y), wc, a1);
            a2 = __hfma2(u2h(qc.z), wc, a2);
            a3 = __hfma2(u2h(qc.w), wc, a3);
            a4 = __hfma2(u2h(rc.x), wc, a4);
            a5 = __hfma2(u2h(rc.y), wc, a5);

            a0 = __hfma2(u2h(qd.x), wd, a0);
            a1 = __hfma2(u2h(qd.y), wd, a1);
            a2 = __hfma2(u2h(qd.z), wd, a2);
            a3 = __hfma2(u2h(qd.w), wd, a3);
            a4 = __hfma2(u2h(rd.x), wd, a4);
            a5 = __hfma2(u2h(rd.y), wd, a5);

            const float2 p0 = __half22float2(a0);
            const float2 p1 = __half22float2(a1);
            const float2 p2 = __half22float2(a2);
            const float2 p3 = __half22float2(a3);
            const float2 p4 = __half22float2(a4);
            const float2 p5 = __half22float2(a5);

            ob[0 * 1048576 + rowoff + px] =
                fmaf(p0.x, R, fmaf(p0.y, G, fmaf(p1.x, Bc, p1.y)));
            ob[1 * 1048576 + rowoff + px] =
                fmaf(p2.x, R, fmaf(p2.y, G, fmaf(p3.x, Bc, p3.y)));
            ob[2 * 1048576 + rowoff + px] =
                fmaf(p4.x, R, fmaf(p4.y, G, fmaf(p5.x, Bc, p5.y)));
        }
    }
}

extern "C" void kernel_launch(void* const* d_in, const int* in_sizes, int n_in,
                              void* d_out, int out_size)
{
    const float* grid  = nullptr;
    const float* guide = nullptr;
    const float* image = nullptr;
    for (int i = 0; i < n_in; ++i) {
        if (in_sizes[i] == 4 * GRID_PER_B)             grid  = (const float*)d_in[i];
        else if (in_sizes[i] == 4 * H_IMG * W_IMG)     guide = (const float*)d_in[i];
        else if (in_sizes[i] == 4 * 3 * H_IMG * W_IMG) image = (const float*)d_in[i];
    }
    float* out = (float*)d_out;

    dim3 gr(H_IMG / ROWS_PER_BLOCK, 4);   // 256 x 4 = 1024 blocks, 4 rows each
    bsa_kernel<<<gr, 256>>>(grid, guide, image, out);
}